// round 1
// baseline (speedup 1.0000x reference)
#include <cuda_runtime.h>
#include <cuda_bf16.h>
#include <cstdint>
#include <math.h>

// ---------------- problem constants (fixed shapes) ----------------
constexpr int B_  = 4;
constexpr int S_  = 2048;
constexpr int H_  = 2048;
constexpr int NH_ = 16;
constexpr int HD_ = 128;
constexpr int KE_ = 8;
constexpr int M_  = B_ * S_;                 // 8192 rows
constexpr float SCALE_ = 0.08838834764831845f;  // 1/sqrt(128)

// ---------------- scratch (device globals; no allocation allowed) ----------------
__device__ float g_q[(long long)M_ * H_];
__device__ float g_k[(long long)M_ * H_];
__device__ float g_v[(long long)M_ * H_];
__device__ float g_ctx[(long long)M_ * H_];
__device__ float g_ao[(long long)M_ * H_];
__device__ float g_ec[(long long)M_ * H_];
__device__ float g_gate[M_ * 2];

// ---------------- helpers ----------------
__device__ __forceinline__ float f2tf32f(float x) {
    uint32_t u;
    asm("cvt.rna.tf32.f32 %0, %1;" : "=r"(u) : "f"(x));
    return __uint_as_float(u);
}

__device__ __forceinline__ void mma_tf32(float c[4], const uint32_t a[4], const uint32_t b[2]) {
    asm volatile(
        "mma.sync.aligned.m16n8k8.row.col.f32.tf32.tf32.f32 "
        "{%0,%1,%2,%3}, {%4,%5,%6,%7}, {%8,%9}, {%0,%1,%2,%3};\n"
        : "+f"(c[0]), "+f"(c[1]), "+f"(c[2]), "+f"(c[3])
        : "r"(a[0]), "r"(a[1]), "r"(a[2]), "r"(a[3]), "r"(b[0]), "r"(b[1]));
}

// ---------------- generic TF32 GEMM: C[M,N] = A[M,K] @ B[K,N] ----------------
// EPI==0: plain store. EPI==1: out = g0[row]*add_src[row,col] + g1[row]*C
constexpr int GBM = 128, GBN = 128, GBK = 16;
constexpr int LDA_ = GBM + 4;
constexpr int LDB_ = GBN + 4;

template <int EPI>
__global__ __launch_bounds__(256)
void gemm_tf32_kernel(const float* __restrict__ A, const float* __restrict__ Bm,
                      float* __restrict__ C, int M, int N, int Kd,
                      const float* __restrict__ add_src,
                      const float* __restrict__ gate) {
    __shared__ float As[GBK][LDA_];   // transposed: As[k][m]
    __shared__ float Bs[GBK][LDB_];   // Bs[k][n]
    const int tid  = threadIdx.x;
    const int w    = tid >> 5, lane = tid & 31;
    const int g    = lane >> 2, tg = lane & 3;
    const int wm   = w >> 1, wn = w & 1;       // 4x2 warp grid
    const int bm   = blockIdx.y * GBM, bn = blockIdx.x * GBN;

    float acc[2][8][4];
#pragma unroll
    for (int i = 0; i < 2; ++i)
#pragma unroll
        for (int j = 0; j < 8; ++j)
#pragma unroll
            for (int t = 0; t < 4; ++t) acc[i][j][t] = 0.f;

    for (int kt = 0; kt < Kd; kt += GBK) {
        // load A tile 128x16 (transpose into As[k][m], convert to tf32)
#pragma unroll
        for (int i = 0; i < 2; ++i) {
            int lin = i * 256 + tid;
            int r = lin >> 2, c4 = lin & 3;
            float4 v = *(const float4*)(A + (size_t)(bm + r) * Kd + kt + c4 * 4);
            As[c4 * 4 + 0][r] = f2tf32f(v.x);
            As[c4 * 4 + 1][r] = f2tf32f(v.y);
            As[c4 * 4 + 2][r] = f2tf32f(v.z);
            As[c4 * 4 + 3][r] = f2tf32f(v.w);
        }
        // load B tile 16x128
#pragma unroll
        for (int i = 0; i < 2; ++i) {
            int lin = i * 256 + tid;
            int r = lin >> 5, c4 = lin & 31;
            float4 v = *(const float4*)(Bm + (size_t)(kt + r) * N + bn + c4 * 4);
            float* d = &Bs[r][c4 * 4];
            d[0] = f2tf32f(v.x); d[1] = f2tf32f(v.y);
            d[2] = f2tf32f(v.z); d[3] = f2tf32f(v.w);
        }
        __syncthreads();

#pragma unroll
        for (int kk = 0; kk < 2; ++kk) {
            uint32_t afr[2][4];
#pragma unroll
            for (int mt = 0; mt < 2; ++mt) {
                int m0 = wm * 32 + mt * 16;
                afr[mt][0] = __float_as_uint(As[kk * 8 + tg][m0 + g]);
                afr[mt][1] = __float_as_uint(As[kk * 8 + tg][m0 + g + 8]);
                afr[mt][2] = __float_as_uint(As[kk * 8 + tg + 4][m0 + g]);
                afr[mt][3] = __float_as_uint(As[kk * 8 + tg + 4][m0 + g + 8]);
            }
#pragma unroll
            for (int nt = 0; nt < 8; ++nt) {
                int n0 = wn * 64 + nt * 8;
                uint32_t bfr[2];
                bfr[0] = __float_as_uint(Bs[kk * 8 + tg][n0 + g]);
                bfr[1] = __float_as_uint(Bs[kk * 8 + tg + 4][n0 + g]);
                mma_tf32(acc[0][nt], afr[0], bfr);
                mma_tf32(acc[1][nt], afr[1], bfr);
            }
        }
        __syncthreads();
    }

    // epilogue
#pragma unroll
    for (int mt = 0; mt < 2; ++mt) {
        int r0 = bm + wm * 32 + mt * 16 + g;
        int r1 = r0 + 8;
        float g0a = 0.f, g1a = 0.f, g0b = 0.f, g1b = 0.f;
        if (EPI == 1) {
            g0a = gate[r0 * 2]; g1a = gate[r0 * 2 + 1];
            g0b = gate[r1 * 2]; g1b = gate[r1 * 2 + 1];
        }
#pragma unroll
        for (int nt = 0; nt < 8; ++nt) {
            int c = bn + wn * 64 + nt * 8 + 2 * tg;
            if (EPI == 0) {
                *(float2*)(C + (size_t)r0 * N + c) = make_float2(acc[mt][nt][0], acc[mt][nt][1]);
                *(float2*)(C + (size_t)r1 * N + c) = make_float2(acc[mt][nt][2], acc[mt][nt][3]);
            } else {
                float2 s0 = *(const float2*)(add_src + (size_t)r0 * N + c);
                float2 s1 = *(const float2*)(add_src + (size_t)r1 * N + c);
                *(float2*)(C + (size_t)r0 * N + c) =
                    make_float2(g0a * s0.x + g1a * acc[mt][nt][0],
                                g0a * s0.y + g1a * acc[mt][nt][1]);
                *(float2*)(C + (size_t)r1 * N + c) =
                    make_float2(g0b * s1.x + g1b * acc[mt][nt][2],
                                g0b * s1.y + g1b * acc[mt][nt][3]);
            }
        }
    }
}

// ---------------- causal flash attention (fp32 in/out, tf32 MMA) ----------------
constexpr int FBR = 128, FBC = 64;
constexpr int FLDQ = HD_ + 4;   // 132
constexpr int FLDP = FBC + 4;   // 68
constexpr int FQ_F = FBR * FLDQ;
constexpr int FK_F = FBC * FLDQ;
constexpr int FV_F = FBC * FLDQ;
constexpr int FP_F = 8 * 16 * FLDP;
constexpr int FLASH_SMEM = (FQ_F + FK_F + FV_F + FP_F) * 4;  // ~166 KB

__global__ __launch_bounds__(256, 1)
void flash_kernel(const float* __restrict__ Q, const float* __restrict__ Kg,
                  const float* __restrict__ Vg, float* __restrict__ O) {
    extern __shared__ float sm[];
    float* Qs = sm;            // [FBR][FLDQ]
    float* Ks = Qs + FQ_F;     // [FBC][FLDQ]
    float* Vs = Ks + FK_F;     // [FBC][FLDQ]
    float* Ps = Vs + FV_F;     // 8 warps * [16][FLDP]

    const int qt = blockIdx.x;
    const int bh = blockIdx.y;
    const int b = bh >> 4, h = bh & 15;
    const int tid = threadIdx.x;
    const int w = tid >> 5, lane = tid & 31;
    const int g = lane >> 2, tg = lane & 3;

    const float* Qbase = Q + ((size_t)(b * S_ + qt * FBR)) * H_ + h * HD_;
    const float* Kbase = Kg + ((size_t)b * S_) * H_ + h * HD_;
    const float* Vbase = Vg + ((size_t)b * S_) * H_ + h * HD_;

    // load Q tile (pre-scaled, tf32)
    for (int i = tid; i < FBR * (HD_ / 4); i += 256) {
        int r = i >> 5, c4 = i & 31;
        float4 v = *(const float4*)(Qbase + (size_t)r * H_ + c4 * 4);
        float* d = Qs + r * FLDQ + c4 * 4;
        d[0] = f2tf32f(v.x * SCALE_);
        d[1] = f2tf32f(v.y * SCALE_);
        d[2] = f2tf32f(v.z * SCALE_);
        d[3] = f2tf32f(v.w * SCALE_);
    }

    float o[16][4];
#pragma unroll
    for (int i = 0; i < 16; ++i)
#pragma unroll
        for (int t = 0; t < 4; ++t) o[i][t] = 0.f;
    float mrow0 = -1e30f, mrow1 = -1e30f, lrow0 = 0.f, lrow1 = 0.f;

    const int rbase = qt * FBR + w * 16;
    const int jmax = (qt * FBR + FBR - 1) / FBC;
    float* pw = Ps + w * 16 * FLDP;

    for (int j = 0; j <= jmax; ++j) {
        __syncthreads();   // previous tile fully consumed
        for (int i = tid; i < FBC * (HD_ / 4); i += 256) {
            int r = i >> 5, c4 = i & 31;
            float4 kv = *(const float4*)(Kbase + (size_t)(j * FBC + r) * H_ + c4 * 4);
            float* d = Ks + r * FLDQ + c4 * 4;
            d[0] = f2tf32f(kv.x); d[1] = f2tf32f(kv.y);
            d[2] = f2tf32f(kv.z); d[3] = f2tf32f(kv.w);
            float4 vv = *(const float4*)(Vbase + (size_t)(j * FBC + r) * H_ + c4 * 4);
            float* d2 = Vs + r * FLDQ + c4 * 4;
            d2[0] = f2tf32f(vv.x); d2[1] = f2tf32f(vv.y);
            d2[2] = f2tf32f(vv.z); d2[3] = f2tf32f(vv.w);
        }
        __syncthreads();

        // S = Q K^T  (each warp: 16 q-rows x 64 kv)
        float sacc[8][4];
#pragma unroll
        for (int nt = 0; nt < 8; ++nt)
#pragma unroll
            for (int t = 0; t < 4; ++t) sacc[nt][t] = 0.f;

#pragma unroll
        for (int kk = 0; kk < HD_ / 8; ++kk) {
            uint32_t afr[4];
            const float* qb = Qs + (w * 16) * FLDQ + kk * 8;
            afr[0] = __float_as_uint(qb[g * FLDQ + tg]);
            afr[1] = __float_as_uint(qb[(g + 8) * FLDQ + tg]);
            afr[2] = __float_as_uint(qb[g * FLDQ + tg + 4]);
            afr[3] = __float_as_uint(qb[(g + 8) * FLDQ + tg + 4]);
#pragma unroll
            for (int nt = 0; nt < 8; ++nt) {
                uint32_t bfr[2];
                bfr[0] = __float_as_uint(Ks[(nt * 8 + g) * FLDQ + kk * 8 + tg]);
                bfr[1] = __float_as_uint(Ks[(nt * 8 + g) * FLDQ + kk * 8 + tg + 4]);
                mma_tf32(sacc[nt], afr, bfr);
            }
        }

        // causal mask
        if (j * FBC + FBC - 1 > rbase) {
#pragma unroll
            for (int nt = 0; nt < 8; ++nt) {
                int c0 = j * FBC + nt * 8 + 2 * tg;
                if (c0 > rbase + g)         sacc[nt][0] = -1e30f;
                if (c0 + 1 > rbase + g)     sacc[nt][1] = -1e30f;
                if (c0 > rbase + g + 8)     sacc[nt][2] = -1e30f;
                if (c0 + 1 > rbase + g + 8) sacc[nt][3] = -1e30f;
            }
        }

        // online softmax (rows g and g+8; stats replicated over the 4 tg lanes)
        float tm0 = -1e30f, tm1 = -1e30f;
#pragma unroll
        for (int nt = 0; nt < 8; ++nt) {
            tm0 = fmaxf(tm0, fmaxf(sacc[nt][0], sacc[nt][1]));
            tm1 = fmaxf(tm1, fmaxf(sacc[nt][2], sacc[nt][3]));
        }
        tm0 = fmaxf(tm0, __shfl_xor_sync(0xffffffffu, tm0, 1));
        tm0 = fmaxf(tm0, __shfl_xor_sync(0xffffffffu, tm0, 2));
        tm1 = fmaxf(tm1, __shfl_xor_sync(0xffffffffu, tm1, 1));
        tm1 = fmaxf(tm1, __shfl_xor_sync(0xffffffffu, tm1, 2));
        float mn0 = fmaxf(mrow0, tm0), mn1 = fmaxf(mrow1, tm1);
        float al0 = __expf(mrow0 - mn0), al1 = __expf(mrow1 - mn1);
        float rs0 = 0.f, rs1 = 0.f;
#pragma unroll
        for (int nt = 0; nt < 8; ++nt) {
            sacc[nt][0] = __expf(sacc[nt][0] - mn0);
            sacc[nt][1] = __expf(sacc[nt][1] - mn0);
            sacc[nt][2] = __expf(sacc[nt][2] - mn1);
            sacc[nt][3] = __expf(sacc[nt][3] - mn1);
            rs0 += sacc[nt][0] + sacc[nt][1];
            rs1 += sacc[nt][2] + sacc[nt][3];
        }
        rs0 += __shfl_xor_sync(0xffffffffu, rs0, 1);
        rs0 += __shfl_xor_sync(0xffffffffu, rs0, 2);
        rs1 += __shfl_xor_sync(0xffffffffu, rs1, 1);
        rs1 += __shfl_xor_sync(0xffffffffu, rs1, 2);
        lrow0 = lrow0 * al0 + rs0;
        lrow1 = lrow1 * al1 + rs1;
        mrow0 = mn0; mrow1 = mn1;
#pragma unroll
        for (int nt = 0; nt < 16; ++nt) {
            o[nt][0] *= al0; o[nt][1] *= al0;
            o[nt][2] *= al1; o[nt][3] *= al1;
        }

        // stage P (tf32) through per-warp smem to re-fragment for PV
#pragma unroll
        for (int nt = 0; nt < 8; ++nt) {
            int c = nt * 8 + 2 * tg;
            pw[g * FLDP + c]           = f2tf32f(sacc[nt][0]);
            pw[g * FLDP + c + 1]       = f2tf32f(sacc[nt][1]);
            pw[(g + 8) * FLDP + c]     = f2tf32f(sacc[nt][2]);
            pw[(g + 8) * FLDP + c + 1] = f2tf32f(sacc[nt][3]);
        }
        __syncwarp();

        // O += P @ V
#pragma unroll
        for (int kt = 0; kt < FBC / 8; ++kt) {
            uint32_t afr[4];
            afr[0] = __float_as_uint(pw[g * FLDP + kt * 8 + tg]);
            afr[1] = __float_as_uint(pw[(g + 8) * FLDP + kt * 8 + tg]);
            afr[2] = __float_as_uint(pw[g * FLDP + kt * 8 + tg + 4]);
            afr[3] = __float_as_uint(pw[(g + 8) * FLDP + kt * 8 + tg + 4]);
#pragma unroll
            for (int nt = 0; nt < 16; ++nt) {
                uint32_t bfr[2];
                bfr[0] = __float_as_uint(Vs[(kt * 8 + tg) * FLDQ + nt * 8 + g]);
                bfr[1] = __float_as_uint(Vs[(kt * 8 + tg + 4) * FLDQ + nt * 8 + g]);
                mma_tf32(o[nt], afr, bfr);
            }
        }
    }

    float inv0 = 1.f / lrow0, inv1 = 1.f / lrow1;
    float* Obase = O + ((size_t)(b * S_ + rbase)) * H_ + h * HD_;
#pragma unroll
    for (int nt = 0; nt < 16; ++nt) {
        int c = nt * 8 + 2 * tg;
        *(float2*)(Obase + (size_t)g * H_ + c) =
            make_float2(o[nt][0] * inv0, o[nt][1] * inv0);
        *(float2*)(Obase + (size_t)(g + 8) * H_ + c) =
            make_float2(o[nt][2] * inv1, o[nt][3] * inv1);
    }
}

// ---------------- external memory attention (memory bound) ----------------
__global__ __launch_bounds__(256)
void ext_attn_kernel(const float* __restrict__ AO, const float* __restrict__ EK,
                     const float* __restrict__ EV, float* __restrict__ EC) {
    int widx = (blockIdx.x * blockDim.x + threadIdx.x) >> 5;   // (b,h,q) index
    int lane = threadIdx.x & 31;
    int q  = widx & (S_ - 1);
    int bh = widx >> 11;          // /S_
    int b = bh >> 4, h = bh & 15;

    size_t aoff = ((size_t)b * S_ + q) * H_ + h * HD_ + lane * 4;
    float4 eq = *(const float4*)(AO + aoff);
    eq.x *= SCALE_; eq.y *= SCALE_; eq.z *= SCALE_; eq.w *= SCALE_;

    size_t base = ((size_t)bh * S_ + q) * (KE_ * HD_) + lane * 4;
    float s[KE_];
#pragma unroll
    for (int kk = 0; kk < KE_; ++kk) {
        float4 kv = *(const float4*)(EK + base + kk * HD_);
        s[kk] = eq.x * kv.x + eq.y * kv.y + eq.z * kv.z + eq.w * kv.w;
    }
#pragma unroll
    for (int kk = 0; kk < KE_; ++kk)
#pragma unroll
        for (int off = 16; off > 0; off >>= 1)
            s[kk] += __shfl_xor_sync(0xffffffffu, s[kk], off);

    float m = s[0];
#pragma unroll
    for (int kk = 1; kk < KE_; ++kk) m = fmaxf(m, s[kk]);
    float sum = 0.f;
#pragma unroll
    for (int kk = 0; kk < KE_; ++kk) { s[kk] = __expf(s[kk] - m); sum += s[kk]; }
    float inv = 1.f / sum;

    float4 acc = make_float4(0.f, 0.f, 0.f, 0.f);
#pragma unroll
    for (int kk = 0; kk < KE_; ++kk) {
        float4 vv = *(const float4*)(EV + base + kk * HD_);
        float wgt = s[kk] * inv;
        acc.x += wgt * vv.x; acc.y += wgt * vv.y;
        acc.z += wgt * vv.z; acc.w += wgt * vv.w;
    }
    *(float4*)(EC + aoff) = acc;
}

// ---------------- gate: softmax over first two of X @ W_gate + b ----------------
__global__ __launch_bounds__(256)
void gate_kernel(const float* __restrict__ X, const float* __restrict__ Wg,
                 const float* __restrict__ bg, float* __restrict__ gate) {
    int row  = (blockIdx.x * blockDim.x + threadIdx.x) >> 5;
    int lane = threadIdx.x & 31;
    const float* xr = X + (size_t)row * H_;
    float a0 = 0.f, a1 = 0.f;
    for (int k = lane; k < H_; k += 32) {
        float x = xr[k];
        a0 += x * Wg[k * 3];
        a1 += x * Wg[k * 3 + 1];
    }
#pragma unroll
    for (int off = 16; off > 0; off >>= 1) {
        a0 += __shfl_xor_sync(0xffffffffu, a0, off);
        a1 += __shfl_xor_sync(0xffffffffu, a1, off);
    }
    if (lane == 0) {
        a0 += bg[0]; a1 += bg[1];
        float m = fmaxf(a0, a1);
        float e0 = __expf(a0 - m), e1 = __expf(a1 - m);
        float inv = 1.f / (e0 + e1);
        gate[row * 2]     = e0 * inv;
        gate[row * 2 + 1] = e1 * inv;
    }
}

// ---------------- launch ----------------
extern "C" void kernel_launch(void* const* d_in, const int* in_sizes, int n_in,
                              void* d_out, int out_size) {
    const float* X  = (const float*)d_in[0];
    const float* EK = (const float*)d_in[1];
    const float* EV = (const float*)d_in[2];
    const float* Wq = (const float*)d_in[3];
    const float* Wk = (const float*)d_in[4];
    const float* Wv = (const float*)d_in[5];
    const float* Wo = (const float*)d_in[6];
    const float* We = (const float*)d_in[7];
    const float* Wg = (const float*)d_in[8];
    const float* bg = (const float*)d_in[9];
    float* out = (float*)d_out;

    float *q, *k, *v, *ctx, *ao, *ec, *gt;
    cudaGetSymbolAddress((void**)&q,   g_q);
    cudaGetSymbolAddress((void**)&k,   g_k);
    cudaGetSymbolAddress((void**)&v,   g_v);
    cudaGetSymbolAddress((void**)&ctx, g_ctx);
    cudaGetSymbolAddress((void**)&ao,  g_ao);
    cudaGetSymbolAddress((void**)&ec,  g_ec);
    cudaGetSymbolAddress((void**)&gt,  g_gate);

    dim3 ggrid(H_ / GBN, M_ / GBM);   // (16, 64)

    gemm_tf32_kernel<0><<<ggrid, 256>>>(X, Wq, q, M_, H_, H_, nullptr, nullptr);
    gemm_tf32_kernel<0><<<ggrid, 256>>>(X, Wk, k, M_, H_, H_, nullptr, nullptr);
    gemm_tf32_kernel<0><<<ggrid, 256>>>(X, Wv, v, M_, H_, H_, nullptr, nullptr);

    cudaFuncSetAttribute(flash_kernel, cudaFuncAttributeMaxDynamicSharedMemorySize, FLASH_SMEM);
    flash_kernel<<<dim3(S_ / FBR, B_ * NH_), 256, FLASH_SMEM>>>(q, k, v, ctx);

    gemm_tf32_kernel<0><<<ggrid, 256>>>(ctx, Wo, ao, M_, H_, H_, nullptr, nullptr);

    gate_kernel<<<M_ / 8, 256>>>(X, Wg, bg, gt);
    ext_attn_kernel<<<(B_ * NH_ * S_) / 8, 256>>>(ao, EK, EV, ec);

    gemm_tf32_kernel<1><<<ggrid, 256>>>(ec, We, out, M_, H_, H_, ao, gt);
}

// round 3
// speedup vs baseline: 1.4807x; 1.4807x over previous
#include <cuda_runtime.h>
#include <cuda_bf16.h>
#include <cstdint>
#include <math.h>

// ---------------- problem constants (fixed shapes) ----------------
constexpr int B_  = 4;
constexpr int S_  = 2048;
constexpr int H_  = 2048;
constexpr int NH_ = 16;
constexpr int HD_ = 128;
constexpr int KE_ = 8;
constexpr int M_  = B_ * S_;                 // 8192 rows
constexpr float SCALE_ = 0.08838834764831845f;  // 1/sqrt(128)

// ---------------- scratch (device globals; no allocation allowed) ----------------
__device__ float g_q[(long long)M_ * H_];
__device__ float g_k[(long long)M_ * H_];
__device__ float g_v[(long long)M_ * H_];
__device__ float g_ctx[(long long)M_ * H_];
__device__ float g_ao[(long long)M_ * H_];
__device__ float g_ec[(long long)M_ * H_];
__device__ float g_gate[M_ * 2];

// ---------------- helpers ----------------
__device__ __forceinline__ float f2tf32f(float x) {
    uint32_t u;
    asm("cvt.rna.tf32.f32 %0, %1;" : "=r"(u) : "f"(x));
    return __uint_as_float(u);
}
__device__ __forceinline__ uint32_t f2tf32u(float x) {
    uint32_t u;
    asm("cvt.rna.tf32.f32 %0, %1;" : "=r"(u) : "f"(x));
    return u;
}

__device__ __forceinline__ void mma_tf32(float c[4], const uint32_t a[4], const uint32_t b[2]) {
    asm volatile(
        "mma.sync.aligned.m16n8k8.row.col.f32.tf32.tf32.f32 "
        "{%0,%1,%2,%3}, {%4,%5,%6,%7}, {%8,%9}, {%0,%1,%2,%3};\n"
        : "+f"(c[0]), "+f"(c[1]), "+f"(c[2]), "+f"(c[3])
        : "r"(a[0]), "r"(a[1]), "r"(a[2]), "r"(a[3]), "r"(b[0]), "r"(b[1]));
}

__device__ __forceinline__ void cpa16(uint32_t dst, const void* src) {
    asm volatile("cp.async.cg.shared.global [%0], [%1], 16;\n" :: "r"(dst), "l"(src));
}

// ---------------- TF32 GEMM with cp.async double buffering ----------------
// C[M,N] = A[M,K] @ B[K,N]
// EPI==0: plain store. EPI==1: out = g0[row]*add_src[row,col] + g1[row]*C
constexpr int GBM = 128, GBN = 128, GBK = 32;
constexpr int LDA_ = GBK + 4;     // 36 floats: row stride of As[m][k]
constexpr int LDB_ = GBN + 8;     // 136 floats: row stride of Bs[k][n]
constexpr int STG_A = GBM * LDA_; // 4608 floats
constexpr int STG_B = GBK * LDB_; // 4352 floats
constexpr int STG   = STG_A + STG_B;
constexpr int GEMM_SMEM = 2 * STG * 4;   // ~70 KB

template <int EPI>
__global__ __launch_bounds__(256, 2)
void gemm_tf32_kernel(const float* __restrict__ A, const float* __restrict__ Bm,
                      float* __restrict__ C, int M, int N, int Kd,
                      const float* __restrict__ add_src,
                      const float* __restrict__ gate) {
    extern __shared__ float sm[];
    const int tid  = threadIdx.x;
    const int w    = tid >> 5, lane = tid & 31;
    const int g    = lane >> 2, tg = lane & 3;
    const int wm   = w >> 1, wn = w & 1;       // 4x2 warp grid
    const int bm   = blockIdx.y * GBM, bn = blockIdx.x * GBN;

    float acc[2][8][4];
#pragma unroll
    for (int i = 0; i < 2; ++i)
#pragma unroll
        for (int j = 0; j < 8; ++j)
#pragma unroll
            for (int t = 0; t < 4; ++t) acc[i][j][t] = 0.f;

    // async tile loader: A tile 128x32 (row-major, padded), B tile 32x128
    auto load_tile = [&](int kt, int stage) {
        float* As = sm + stage * STG;
        float* Bs = As + STG_A;
#pragma unroll
        for (int i = 0; i < 4; ++i) {
            int lin = i * 256 + tid;
            int r = lin >> 3, c = lin & 7;
            cpa16((uint32_t)__cvta_generic_to_shared(As + r * LDA_ + c * 4),
                  A + (size_t)(bm + r) * Kd + kt + c * 4);
        }
#pragma unroll
        for (int i = 0; i < 4; ++i) {
            int lin = i * 256 + tid;
            int r = lin >> 5, c = lin & 31;
            cpa16((uint32_t)__cvta_generic_to_shared(Bs + r * LDB_ + c * 4),
                  Bm + (size_t)(kt + r) * N + bn + c * 4);
        }
        asm volatile("cp.async.commit_group;\n");
    };

    load_tile(0, 0);

    const int m0base = wm * 32;
    const int n0base = wn * 64;

    for (int kt = 0; kt < Kd; kt += GBK) {
        int st = (kt / GBK) & 1;
        if (kt + GBK < Kd) {
            load_tile(kt + GBK, st ^ 1);
            asm volatile("cp.async.wait_group 1;\n");
        } else {
            asm volatile("cp.async.wait_group 0;\n");
        }
        __syncthreads();

        const float* As = sm + st * STG;
        const float* Bs = As + STG_A;

#pragma unroll
        for (int kk = 0; kk < GBK / 8; ++kk) {
            uint32_t afr[2][4];
#pragma unroll
            for (int mt = 0; mt < 2; ++mt) {
                const float* ab = As + (m0base + mt * 16) * LDA_ + kk * 8;
                afr[mt][0] = f2tf32u(ab[g * LDA_ + tg]);
                afr[mt][1] = f2tf32u(ab[(g + 8) * LDA_ + tg]);
                afr[mt][2] = f2tf32u(ab[g * LDA_ + tg + 4]);
                afr[mt][3] = f2tf32u(ab[(g + 8) * LDA_ + tg + 4]);
            }
#pragma unroll
            for (int nt = 0; nt < 8; ++nt) {
                int n0 = n0base + nt * 8;
                uint32_t bfr[2];
                bfr[0] = f2tf32u(Bs[(kk * 8 + tg) * LDB_ + n0 + g]);
                bfr[1] = f2tf32u(Bs[(kk * 8 + tg + 4) * LDB_ + n0 + g]);
                mma_tf32(acc[0][nt], afr[0], bfr);
                mma_tf32(acc[1][nt], afr[1], bfr);
            }
        }
        __syncthreads();
    }

    // epilogue
#pragma unroll
    for (int mt = 0; mt < 2; ++mt) {
        int r0 = bm + wm * 32 + mt * 16 + g;
        int r1 = r0 + 8;
        float g0a = 0.f, g1a = 0.f, g0b = 0.f, g1b = 0.f;
        if (EPI == 1) {
            g0a = gate[r0 * 2]; g1a = gate[r0 * 2 + 1];
            g0b = gate[r1 * 2]; g1b = gate[r1 * 2 + 1];
        }
#pragma unroll
        for (int nt = 0; nt < 8; ++nt) {
            int c = bn + wn * 64 + nt * 8 + 2 * tg;
            if (EPI == 0) {
                *(float2*)(C + (size_t)r0 * N + c) = make_float2(acc[mt][nt][0], acc[mt][nt][1]);
                *(float2*)(C + (size_t)r1 * N + c) = make_float2(acc[mt][nt][2], acc[mt][nt][3]);
            } else {
                float2 s0 = *(const float2*)(add_src + (size_t)r0 * N + c);
                float2 s1 = *(const float2*)(add_src + (size_t)r1 * N + c);
                *(float2*)(C + (size_t)r0 * N + c) =
                    make_float2(g0a * s0.x + g1a * acc[mt][nt][0],
                                g0a * s0.y + g1a * acc[mt][nt][1]);
                *(float2*)(C + (size_t)r1 * N + c) =
                    make_float2(g0b * s1.x + g1b * acc[mt][nt][2],
                                g0b * s1.y + g1b * acc[mt][nt][3]);
            }
        }
    }
}

// ---------------- causal flash attention (fp32 in/out, tf32 MMA) ----------------
constexpr int FBR = 128, FBC = 64;
constexpr int FLDQ = HD_ + 4;   // 132
constexpr int FLDP = FBC + 4;   // 68
constexpr int FQ_F = FBR * FLDQ;
constexpr int FK_F = FBC * FLDQ;
constexpr int FV_F = FBC * FLDQ;
constexpr int FP_F = 8 * 16 * FLDP;
constexpr int FLASH_SMEM = (FQ_F + FK_F + FV_F + FP_F) * 4;  // ~166 KB

__global__ __launch_bounds__(256, 1)
void flash_kernel(const float* __restrict__ Q, const float* __restrict__ Kg,
                  const float* __restrict__ Vg, float* __restrict__ O) {
    extern __shared__ float sm[];
    float* Qs = sm;            // [FBR][FLDQ]
    float* Ks = Qs + FQ_F;     // [FBC][FLDQ]
    float* Vs = Ks + FK_F;     // [FBC][FLDQ]
    float* Ps = Vs + FV_F;     // 8 warps * [16][FLDP]

    const int qt = blockIdx.x;
    const int bh = blockIdx.y;
    const int b = bh >> 4, h = bh & 15;
    const int tid = threadIdx.x;
    const int w = tid >> 5, lane = tid & 31;
    const int g = lane >> 2, tg = lane & 3;

    const float* Qbase = Q + ((size_t)(b * S_ + qt * FBR)) * H_ + h * HD_;
    const float* Kbase = Kg + ((size_t)b * S_) * H_ + h * HD_;
    const float* Vbase = Vg + ((size_t)b * S_) * H_ + h * HD_;

    // load Q tile (pre-scaled, tf32)
    for (int i = tid; i < FBR * (HD_ / 4); i += 256) {
        int r = i >> 5, c4 = i & 31;
        float4 v = *(const float4*)(Qbase + (size_t)r * H_ + c4 * 4);
        float* d = Qs + r * FLDQ + c4 * 4;
        d[0] = f2tf32f(v.x * SCALE_);
        d[1] = f2tf32f(v.y * SCALE_);
        d[2] = f2tf32f(v.z * SCALE_);
        d[3] = f2tf32f(v.w * SCALE_);
    }

    float o[16][4];
#pragma unroll
    for (int i = 0; i < 16; ++i)
#pragma unroll
        for (int t = 0; t < 4; ++t) o[i][t] = 0.f;
    float mrow0 = -1e30f, mrow1 = -1e30f, lrow0 = 0.f, lrow1 = 0.f;

    const int rbase = qt * FBR + w * 16;
    const int jmax = (qt * FBR + FBR - 1) / FBC;
    float* pw = Ps + w * 16 * FLDP;

    for (int j = 0; j <= jmax; ++j) {
        __syncthreads();   // previous tile fully consumed
        for (int i = tid; i < FBC * (HD_ / 4); i += 256) {
            int r = i >> 5, c4 = i & 31;
            float4 kv = *(const float4*)(Kbase + (size_t)(j * FBC + r) * H_ + c4 * 4);
            float* d = Ks + r * FLDQ + c4 * 4;
            d[0] = f2tf32f(kv.x); d[1] = f2tf32f(kv.y);
            d[2] = f2tf32f(kv.z); d[3] = f2tf32f(kv.w);
            float4 vv = *(const float4*)(Vbase + (size_t)(j * FBC + r) * H_ + c4 * 4);
            float* d2 = Vs + r * FLDQ + c4 * 4;
            d2[0] = f2tf32f(vv.x); d2[1] = f2tf32f(vv.y);
            d2[2] = f2tf32f(vv.z); d2[3] = f2tf32f(vv.w);
        }
        __syncthreads();

        // S = Q K^T  (each warp: 16 q-rows x 64 kv)
        float sacc[8][4];
#pragma unroll
        for (int nt = 0; nt < 8; ++nt)
#pragma unroll
            for (int t = 0; t < 4; ++t) sacc[nt][t] = 0.f;

#pragma unroll
        for (int kk = 0; kk < HD_ / 8; ++kk) {
            uint32_t afr[4];
            const float* qb = Qs + (w * 16) * FLDQ + kk * 8;
            afr[0] = __float_as_uint(qb[g * FLDQ + tg]);
            afr[1] = __float_as_uint(qb[(g + 8) * FLDQ + tg]);
            afr[2] = __float_as_uint(qb[g * FLDQ + tg + 4]);
            afr[3] = __float_as_uint(qb[(g + 8) * FLDQ + tg + 4]);
#pragma unroll
            for (int nt = 0; nt < 8; ++nt) {
                uint32_t bfr[2];
                bfr[0] = __float_as_uint(Ks[(nt * 8 + g) * FLDQ + kk * 8 + tg]);
                bfr[1] = __float_as_uint(Ks[(nt * 8 + g) * FLDQ + kk * 8 + tg + 4]);
                mma_tf32(sacc[nt], afr, bfr);
            }
        }

        // causal mask
        if (j * FBC + FBC - 1 > rbase) {
#pragma unroll
            for (int nt = 0; nt < 8; ++nt) {
                int c0 = j * FBC + nt * 8 + 2 * tg;
                if (c0 > rbase + g)         sacc[nt][0] = -1e30f;
                if (c0 + 1 > rbase + g)     sacc[nt][1] = -1e30f;
                if (c0 > rbase + g + 8)     sacc[nt][2] = -1e30f;
                if (c0 + 1 > rbase + g + 8) sacc[nt][3] = -1e30f;
            }
        }

        // online softmax (rows g and g+8; stats replicated over the 4 tg lanes)
        float tm0 = -1e30f, tm1 = -1e30f;
#pragma unroll
        for (int nt = 0; nt < 8; ++nt) {
            tm0 = fmaxf(tm0, fmaxf(sacc[nt][0], sacc[nt][1]));
            tm1 = fmaxf(tm1, fmaxf(sacc[nt][2], sacc[nt][3]));
        }
        tm0 = fmaxf(tm0, __shfl_xor_sync(0xffffffffu, tm0, 1));
        tm0 = fmaxf(tm0, __shfl_xor_sync(0xffffffffu, tm0, 2));
        tm1 = fmaxf(tm1, __shfl_xor_sync(0xffffffffu, tm1, 1));
        tm1 = fmaxf(tm1, __shfl_xor_sync(0xffffffffu, tm1, 2));
        float mn0 = fmaxf(mrow0, tm0), mn1 = fmaxf(mrow1, tm1);
        float al0 = __expf(mrow0 - mn0), al1 = __expf(mrow1 - mn1);
        float rs0 = 0.f, rs1 = 0.f;
#pragma unroll
        for (int nt = 0; nt < 8; ++nt) {
            sacc[nt][0] = __expf(sacc[nt][0] - mn0);
            sacc[nt][1] = __expf(sacc[nt][1] - mn0);
            sacc[nt][2] = __expf(sacc[nt][2] - mn1);
            sacc[nt][3] = __expf(sacc[nt][3] - mn1);
            rs0 += sacc[nt][0] + sacc[nt][1];
            rs1 += sacc[nt][2] + sacc[nt][3];
        }
        rs0 += __shfl_xor_sync(0xffffffffu, rs0, 1);
        rs0 += __shfl_xor_sync(0xffffffffu, rs0, 2);
        rs1 += __shfl_xor_sync(0xffffffffu, rs1, 1);
        rs1 += __shfl_xor_sync(0xffffffffu, rs1, 2);
        lrow0 = lrow0 * al0 + rs0;
        lrow1 = lrow1 * al1 + rs1;
        mrow0 = mn0; mrow1 = mn1;
#pragma unroll
        for (int nt = 0; nt < 16; ++nt) {
            o[nt][0] *= al0; o[nt][1] *= al0;
            o[nt][2] *= al1; o[nt][3] *= al1;
        }

        // stage P (tf32) through per-warp smem to re-fragment for PV
#pragma unroll
        for (int nt = 0; nt < 8; ++nt) {
            int c = nt * 8 + 2 * tg;
            pw[g * FLDP + c]           = f2tf32f(sacc[nt][0]);
            pw[g * FLDP + c + 1]       = f2tf32f(sacc[nt][1]);
            pw[(g + 8) * FLDP + c]     = f2tf32f(sacc[nt][2]);
            pw[(g + 8) * FLDP + c + 1] = f2tf32f(sacc[nt][3]);
        }
        __syncwarp();

        // O += P @ V
#pragma unroll
        for (int kt = 0; kt < FBC / 8; ++kt) {
            uint32_t afr[4];
            afr[0] = __float_as_uint(pw[g * FLDP + kt * 8 + tg]);
            afr[1] = __float_as_uint(pw[(g + 8) * FLDP + kt * 8 + tg]);
            afr[2] = __float_as_uint(pw[g * FLDP + kt * 8 + tg + 4]);
            afr[3] = __float_as_uint(pw[(g + 8) * FLDP + kt * 8 + tg + 4]);
#pragma unroll
            for (int nt = 0; nt < 16; ++nt) {
                uint32_t bfr[2];
                bfr[0] = __float_as_uint(Vs[(kt * 8 + tg) * FLDQ + nt * 8 + g]);
                bfr[1] = __float_as_uint(Vs[(kt * 8 + tg + 4) * FLDQ + nt * 8 + g]);
                mma_tf32(o[nt], afr, bfr);
            }
        }
    }

    float inv0 = 1.f / lrow0, inv1 = 1.f / lrow1;
    float* Obase = O + ((size_t)(b * S_ + rbase)) * H_ + h * HD_;
#pragma unroll
    for (int nt = 0; nt < 16; ++nt) {
        int c = nt * 8 + 2 * tg;
        *(float2*)(Obase + (size_t)g * H_ + c) =
            make_float2(o[nt][0] * inv0, o[nt][1] * inv0);
        *(float2*)(Obase + (size_t)(g + 8) * H_ + c) =
            make_float2(o[nt][2] * inv1, o[nt][3] * inv1);
    }
}

// ---------------- external memory attention (memory bound) ----------------
__global__ __launch_bounds__(256)
void ext_attn_kernel(const float* __restrict__ AO, const float* __restrict__ EK,
                     const float* __restrict__ EV, float* __restrict__ EC) {
    int widx = (blockIdx.x * blockDim.x + threadIdx.x) >> 5;   // (b,h,q) index
    int lane = threadIdx.x & 31;
    int q  = widx & (S_ - 1);
    int bh = widx >> 11;          // /S_
    int b = bh >> 4, h = bh & 15;

    size_t aoff = ((size_t)b * S_ + q) * H_ + h * HD_ + lane * 4;
    float4 eq = *(const float4*)(AO + aoff);
    eq.x *= SCALE_; eq.y *= SCALE_; eq.z *= SCALE_; eq.w *= SCALE_;

    size_t base = ((size_t)bh * S_ + q) * (KE_ * HD_) + lane * 4;
    float s[KE_];
#pragma unroll
    for (int kk = 0; kk < KE_; ++kk) {
        float4 kv = *(const float4*)(EK + base + kk * HD_);
        s[kk] = eq.x * kv.x + eq.y * kv.y + eq.z * kv.z + eq.w * kv.w;
    }
#pragma unroll
    for (int kk = 0; kk < KE_; ++kk)
#pragma unroll
        for (int off = 16; off > 0; off >>= 1)
            s[kk] += __shfl_xor_sync(0xffffffffu, s[kk], off);

    float m = s[0];
#pragma unroll
    for (int kk = 1; kk < KE_; ++kk) m = fmaxf(m, s[kk]);
    float sum = 0.f;
#pragma unroll
    for (int kk = 0; kk < KE_; ++kk) { s[kk] = __expf(s[kk] - m); sum += s[kk]; }
    float inv = 1.f / sum;

    float4 acc = make_float4(0.f, 0.f, 0.f, 0.f);
#pragma unroll
    for (int kk = 0; kk < KE_; ++kk) {
        float4 vv = *(const float4*)(EV + base + kk * HD_);
        float wgt = s[kk] * inv;
        acc.x += wgt * vv.x; acc.y += wgt * vv.y;
        acc.z += wgt * vv.z; acc.w += wgt * vv.w;
    }
    *(float4*)(EC + aoff) = acc;
}

// ---------------- gate: softmax over first two of X @ W_gate + b ----------------
__global__ __launch_bounds__(256)
void gate_kernel(const float* __restrict__ X, const float* __restrict__ Wg,
                 const float* __restrict__ bg, float* __restrict__ gate) {
    int row  = (blockIdx.x * blockDim.x + threadIdx.x) >> 5;
    int lane = threadIdx.x & 31;
    const float* xr = X + (size_t)row * H_;
    float a0 = 0.f, a1 = 0.f;
    for (int k = lane; k < H_; k += 32) {
        float x = xr[k];
        a0 += x * Wg[k * 3];
        a1 += x * Wg[k * 3 + 1];
    }
#pragma unroll
    for (int off = 16; off > 0; off >>= 1) {
        a0 += __shfl_xor_sync(0xffffffffu, a0, off);
        a1 += __shfl_xor_sync(0xffffffffu, a1, off);
    }
    if (lane == 0) {
        a0 += bg[0]; a1 += bg[1];
        float m = fmaxf(a0, a1);
        float e0 = __expf(a0 - m), e1 = __expf(a1 - m);
        float inv = 1.f / (e0 + e1);
        gate[row * 2]     = e0 * inv;
        gate[row * 2 + 1] = e1 * inv;
    }
}

// ---------------- launch ----------------
extern "C" void kernel_launch(void* const* d_in, const int* in_sizes, int n_in,
                              void* d_out, int out_size) {
    const float* X  = (const float*)d_in[0];
    const float* EK = (const float*)d_in[1];
    const float* EV = (const float*)d_in[2];
    const float* Wq = (const float*)d_in[3];
    const float* Wk = (const float*)d_in[4];
    const float* Wv = (const float*)d_in[5];
    const float* Wo = (const float*)d_in[6];
    const float* We = (const float*)d_in[7];
    const float* Wg = (const float*)d_in[8];
    const float* bg = (const float*)d_in[9];
    float* out = (float*)d_out;

    float *q, *k, *v, *ctx, *ao, *ec, *gt;
    cudaGetSymbolAddress((void**)&q,   g_q);
    cudaGetSymbolAddress((void**)&k,   g_k);
    cudaGetSymbolAddress((void**)&v,   g_v);
    cudaGetSymbolAddress((void**)&ctx, g_ctx);
    cudaGetSymbolAddress((void**)&ao,  g_ao);
    cudaGetSymbolAddress((void**)&ec,  g_ec);
    cudaGetSymbolAddress((void**)&gt,  g_gate);

    cudaFuncSetAttribute(gemm_tf32_kernel<0>, cudaFuncAttributeMaxDynamicSharedMemorySize, GEMM_SMEM);
    cudaFuncSetAttribute(gemm_tf32_kernel<1>, cudaFuncAttributeMaxDynamicSharedMemorySize, GEMM_SMEM);
    cudaFuncSetAttribute(flash_kernel, cudaFuncAttributeMaxDynamicSharedMemorySize, FLASH_SMEM);

    dim3 ggrid(H_ / GBN, M_ / GBM);   // (16, 64)

    gemm_tf32_kernel<0><<<ggrid, 256, GEMM_SMEM>>>(X, Wq, q, M_, H_, H_, nullptr, nullptr);
    gemm_tf32_kernel<0><<<ggrid, 256, GEMM_SMEM>>>(X, Wk, k, M_, H_, H_, nullptr, nullptr);
    gemm_tf32_kernel<0><<<ggrid, 256, GEMM_SMEM>>>(X, Wv, v, M_, H_, H_, nullptr, nullptr);

    flash_kernel<<<dim3(S_ / FBR, B_ * NH_), 256, FLASH_SMEM>>>(q, k, v, ctx);

    gemm_tf32_kernel<0><<<ggrid, 256, GEMM_SMEM>>>(ctx, Wo, ao, M_, H_, H_, nullptr, nullptr);

    gate_kernel<<<M_ / 8, 256>>>(X, Wg, bg, gt);
    ext_attn_kernel<<<(B_ * NH_ * S_) / 8, 256>>>(ao, EK, EV, ec);

    gemm_tf32_kernel<1><<<ggrid, 256, GEMM_SMEM>>>(ec, We, out, M_, H_, H_, ao, gt);
}

// round 4
// speedup vs baseline: 1.5955x; 1.0775x over previous
#include <cuda_runtime.h>
#include <cuda_bf16.h>
#include <cstdint>
#include <math.h>

// ---------------- problem constants (fixed shapes) ----------------
constexpr int B_  = 4;
constexpr int S_  = 2048;
constexpr int H_  = 2048;
constexpr int NH_ = 16;
constexpr int HD_ = 128;
constexpr int KE_ = 8;
constexpr int M_  = B_ * S_;                 // 8192 rows
constexpr float SCALE_ = 0.08838834764831845f;  // 1/sqrt(128)

// ---------------- scratch (device globals; no allocation allowed) ----------------
__device__ float g_q[(long long)M_ * H_];
__device__ float g_k[(long long)M_ * H_];
__device__ float g_v[(long long)M_ * H_];
__device__ float g_ctx[(long long)M_ * H_];
__device__ float g_ao[(long long)M_ * H_];
__device__ float g_ec[(long long)M_ * H_];
__device__ float g_xt[(long long)M_ * H_];      // tf32-rounded copy of X
__device__ float g_wt[5][(long long)H_ * H_];   // transposed+tf32 weights
__device__ float g_gate[M_ * 2];

// ---------------- helpers ----------------
__device__ __forceinline__ float f2tf32f(float x) {
    uint32_t u;
    asm("cvt.rna.tf32.f32 %0, %1;" : "=r"(u) : "f"(x));
    return __uint_as_float(u);
}

__device__ __forceinline__ void mma_tf32(float c[4], const uint32_t a[4], const uint32_t b[2]) {
    asm volatile(
        "mma.sync.aligned.m16n8k8.row.col.f32.tf32.tf32.f32 "
        "{%0,%1,%2,%3}, {%4,%5,%6,%7}, {%8,%9}, {%0,%1,%2,%3};\n"
        : "+f"(c[0]), "+f"(c[1]), "+f"(c[2]), "+f"(c[3])
        : "r"(a[0]), "r"(a[1]), "r"(a[2]), "r"(a[3]), "r"(b[0]), "r"(b[1]));
}

__device__ __forceinline__ void cpa16(uint32_t dst, const void* src) {
    asm volatile("cp.async.cg.shared.global [%0], [%1], 16;\n" :: "r"(dst), "l"(src));
}

__device__ __forceinline__ void ldsm4(uint32_t a[4], uint32_t addr) {
    asm volatile("ldmatrix.sync.aligned.m8n8.x4.shared.b16 {%0,%1,%2,%3}, [%4];\n"
        : "=r"(a[0]), "=r"(a[1]), "=r"(a[2]), "=r"(a[3]) : "r"(addr));
}

// ---------------- pre-pass: tf32 convert (elementwise) ----------------
__global__ __launch_bounds__(256)
void cvt_tf32_kernel(const float4* __restrict__ in, float4* __restrict__ out) {
    int i = blockIdx.x * 256 + threadIdx.x;
    float4 v = in[i];
    out[i] = make_float4(f2tf32f(v.x), f2tf32f(v.y), f2tf32f(v.z), f2tf32f(v.w));
}

// ---------------- pre-pass: Wt[n][k] = tf32(W[k][n]) ----------------
__global__ __launch_bounds__(256)
void transpose_tf32_kernel(const float* __restrict__ W, float* __restrict__ Wt) {
    __shared__ float t[32][33];
    int bx = blockIdx.x * 32, by = blockIdx.y * 32;
    int x = threadIdx.x & 31, y0 = threadIdx.x >> 5;   // 32x8
#pragma unroll
    for (int dy = 0; dy < 32; dy += 8)
        t[y0 + dy][x] = W[(size_t)(by + y0 + dy) * H_ + bx + x];
    __syncthreads();
#pragma unroll
    for (int dy = 0; dy < 32; dy += 8)
        Wt[(size_t)(bx + y0 + dy) * H_ + by + x] = f2tf32f(t[x][y0 + dy]);
}

// ---------------- TF32 GEMM v3: ldmatrix + cp.async, 64x64 warp tiles ----------------
// C[8192,2048] = A[8192,2048] @ Bt[n][k]^T, operands pre-rounded to tf32.
// ROUND: store tf32-rounded. EPI: out = g0[row]*add_src + g1[row]*C
constexpr int GLDA = 36;                 // floats per smem row (32 k + 4 pad)
constexpr int GSTG_A = 128 * GLDA;       // 4608 floats
constexpr int GSTG   = 2 * GSTG_A;       // A tile + B tile
constexpr int GEMM_SMEM = 2 * GSTG * 4;  // 73728 B

template <int ROUND, int EPI>
__global__ __launch_bounds__(128, 2)
void gemm_v3(const float* __restrict__ A, const float* __restrict__ Bt,
             float* __restrict__ C,
             const float* __restrict__ add_src, const float* __restrict__ gate) {
    extern __shared__ float sm[];
    const int tid = threadIdx.x, lane = tid & 31, w = tid >> 5;
    const int g = lane >> 2, tg = lane & 3;
    const int wm = w >> 1, wn = w & 1;
    const int bm = blockIdx.y * 128, bn = blockIdx.x * 128;
    const uint32_t smu = (uint32_t)__cvta_generic_to_shared(sm);

    float acc[4][8][4];
#pragma unroll
    for (int t = 0; t < 4; ++t)
#pragma unroll
        for (int n = 0; n < 8; ++n)
#pragma unroll
            for (int i = 0; i < 4; ++i) acc[t][n][i] = 0.f;

    auto load_tile = [&](int kt, int st) {
#pragma unroll
        for (int i = 0; i < 8; ++i) {
            int id = i * 128 + tid;
            int r = id >> 3, c = id & 7;
            cpa16(smu + (uint32_t)(st * GSTG + r * GLDA + c * 4) * 4,
                  A + (size_t)(bm + r) * H_ + kt + c * 4);
        }
#pragma unroll
        for (int i = 0; i < 8; ++i) {
            int id = i * 128 + tid;
            int r = id >> 3, c = id & 7;
            cpa16(smu + (uint32_t)(st * GSTG + GSTG_A + r * GLDA + c * 4) * 4,
                  Bt + (size_t)(bn + r) * H_ + kt + c * 4);
        }
        asm volatile("cp.async.commit_group;\n");
    };

    load_tile(0, 0);

    const uint32_t a_lane = (uint32_t)((lane & 15) * GLDA + ((lane >> 4) << 2)) * 4;
    const uint32_t b_lane = (uint32_t)(((lane & 7) + ((lane & 16) >> 1)) * GLDA + ((lane & 8) >> 1)) * 4;
    const uint32_t aBase = smu + (uint32_t)(wm * 64 * GLDA) * 4 + a_lane;
    const uint32_t bBase = smu + (uint32_t)(GSTG_A + wn * 64 * GLDA) * 4 + b_lane;

    for (int kt = 0; kt < H_; kt += 32) {
        int st = (kt >> 5) & 1;
        if (kt + 32 < H_) {
            load_tile(kt + 32, st ^ 1);
            asm volatile("cp.async.wait_group 1;\n");
        } else {
            asm volatile("cp.async.wait_group 0;\n");
        }
        __syncthreads();

        uint32_t aT = aBase + (uint32_t)(st * GSTG) * 4;
        uint32_t bT = bBase + (uint32_t)(st * GSTG) * 4;
#pragma unroll
        for (int kk = 0; kk < 4; ++kk) {
            uint32_t af[4][4], bf[4][4];
#pragma unroll
            for (int t = 0; t < 4; ++t) ldsm4(af[t], aT + (uint32_t)(t * 16 * GLDA + kk * 8) * 4);
#pragma unroll
            for (int p = 0; p < 4; ++p) ldsm4(bf[p], bT + (uint32_t)(p * 16 * GLDA + kk * 8) * 4);
#pragma unroll
            for (int t = 0; t < 4; ++t)
#pragma unroll
                for (int p = 0; p < 4; ++p) {
                    mma_tf32(acc[t][2 * p],     af[t], &bf[p][0]);
                    mma_tf32(acc[t][2 * p + 1], af[t], &bf[p][2]);
                }
        }
        __syncthreads();
    }

    // epilogue
#pragma unroll
    for (int t = 0; t < 4; ++t) {
        int r0 = bm + wm * 64 + 16 * t + g;
        int r1 = r0 + 8;
        float g0a = 0.f, g1a = 0.f, g0b = 0.f, g1b = 0.f;
        if (EPI == 1) {
            g0a = gate[r0 * 2]; g1a = gate[r0 * 2 + 1];
            g0b = gate[r1 * 2]; g1b = gate[r1 * 2 + 1];
        }
#pragma unroll
        for (int nt = 0; nt < 8; ++nt) {
            int c = bn + wn * 64 + nt * 8 + 2 * tg;
            float v0 = acc[t][nt][0], v1 = acc[t][nt][1];
            float v2 = acc[t][nt][2], v3 = acc[t][nt][3];
            if (EPI == 1) {
                float2 s0 = *(const float2*)(add_src + (size_t)r0 * H_ + c);
                float2 s1 = *(const float2*)(add_src + (size_t)r1 * H_ + c);
                v0 = g0a * s0.x + g1a * v0;  v1 = g0a * s0.y + g1a * v1;
                v2 = g0b * s1.x + g1b * v2;  v3 = g0b * s1.y + g1b * v3;
            }
            if (ROUND == 1) {
                v0 = f2tf32f(v0); v1 = f2tf32f(v1);
                v2 = f2tf32f(v2); v3 = f2tf32f(v3);
            }
            *(float2*)(C + (size_t)r0 * H_ + c) = make_float2(v0, v1);
            *(float2*)(C + (size_t)r1 * H_ + c) = make_float2(v2, v3);
        }
    }
}

// ---------------- causal flash attention v3 ----------------
// inputs q/k/v pre-rounded tf32; cp.async double-buffered K/V (FBC=32)
constexpr int FBR = 128, FBC = 32;
constexpr int LDQ = 132;   // 4g+tg bank pattern: conflict-free
constexpr int LDK = 132;
constexpr int LDV = 136;   // 8tg+g bank pattern: conflict-free
constexpr int LDP = 68;
constexpr int FQ_F = FBR * LDQ;          // 16896
constexpr int FK_F = 2 * FBC * LDK;      // 8448
constexpr int FV_F = 2 * FBC * LDV;      // 8704
constexpr int FP_F = 8 * 16 * LDP;       // 8704
constexpr int FLASH_SMEM = (FQ_F + FK_F + FV_F + FP_F) * 4;  // ~167 KB

__global__ __launch_bounds__(256, 1)
void flash_kernel(const float* __restrict__ Q, const float* __restrict__ Kg,
                  const float* __restrict__ Vg, float* __restrict__ O) {
    extern __shared__ float sm[];
    float* Qs = sm;             // [FBR][LDQ]
    float* Ks = Qs + FQ_F;      // 2 x [FBC][LDK]
    float* Vs = Ks + FK_F;      // 2 x [FBC][LDV]
    float* Ps = Vs + FV_F;      // 8 warps x [16][LDP]
    const uint32_t k_smu = (uint32_t)__cvta_generic_to_shared(Ks);
    const uint32_t v_smu = (uint32_t)__cvta_generic_to_shared(Vs);

    const int qt = blockIdx.x;
    const int bh = blockIdx.y;
    const int b = bh >> 4, h = bh & 15;
    const int tid = threadIdx.x;
    const int w = tid >> 5, lane = tid & 31;
    const int g = lane >> 2, tg = lane & 3;

    const float* Qbase = Q + ((size_t)(b * S_ + qt * FBR)) * H_ + h * HD_;
    const float* Kbase = Kg + ((size_t)b * S_) * H_ + h * HD_;
    const float* Vbase = Vg + ((size_t)b * S_) * H_ + h * HD_;

    auto load_kv = [&](int j, int st) {
        const float* Kb = Kbase + (size_t)(j * FBC) * H_;
        const float* Vb = Vbase + (size_t)(j * FBC) * H_;
#pragma unroll
        for (int i = 0; i < 4; ++i) {
            int id = i * 256 + tid;
            int r = id >> 5, c = id & 31;
            cpa16(k_smu + (uint32_t)(st * FBC * LDK + r * LDK + c * 4) * 4,
                  Kb + (size_t)r * H_ + c * 4);
        }
#pragma unroll
        for (int i = 0; i < 4; ++i) {
            int id = i * 256 + tid;
            int r = id >> 5, c = id & 31;
            cpa16(v_smu + (uint32_t)(st * FBC * LDV + r * LDV + c * 4) * 4,
                  Vb + (size_t)r * H_ + c * 4);
        }
        asm volatile("cp.async.commit_group;\n");
    };

    load_kv(0, 0);

    // load Q tile (scale + round)
    for (int i = tid; i < FBR * (HD_ / 4); i += 256) {
        int r = i >> 5, c4 = i & 31;
        float4 v = *(const float4*)(Qbase + (size_t)r * H_ + c4 * 4);
        float* d = Qs + r * LDQ + c4 * 4;
        d[0] = f2tf32f(v.x * SCALE_);
        d[1] = f2tf32f(v.y * SCALE_);
        d[2] = f2tf32f(v.z * SCALE_);
        d[3] = f2tf32f(v.w * SCALE_);
    }

    float o[16][4];
#pragma unroll
    for (int i = 0; i < 16; ++i)
#pragma unroll
        for (int t = 0; t < 4; ++t) o[i][t] = 0.f;
    float mrow0 = -1e30f, mrow1 = -1e30f, lrow0 = 0.f, lrow1 = 0.f;

    const int rbase = qt * FBR + w * 16;
    const int jmax = 4 * qt + 3;
    float* pw = Ps + w * 16 * LDP;

    for (int j = 0; j <= jmax; ++j) {
        int st = j & 1;
        if (j < jmax) {
            load_kv(j + 1, st ^ 1);
            asm volatile("cp.async.wait_group 1;\n");
        } else {
            asm volatile("cp.async.wait_group 0;\n");
        }
        __syncthreads();

        const float* Kst = Ks + st * FBC * LDK;
        const float* Vst = Vs + st * FBC * LDV;

        // S = Q K^T : warp computes 16 q-rows x 32 kv
        float sacc[4][4];
#pragma unroll
        for (int nt = 0; nt < 4; ++nt)
#pragma unroll
            for (int t = 0; t < 4; ++t) sacc[nt][t] = 0.f;

#pragma unroll
        for (int kk = 0; kk < HD_ / 8; ++kk) {
            uint32_t afr[4];
            const float* qb = Qs + (w * 16) * LDQ + kk * 8;
            afr[0] = __float_as_uint(qb[g * LDQ + tg]);
            afr[1] = __float_as_uint(qb[(g + 8) * LDQ + tg]);
            afr[2] = __float_as_uint(qb[g * LDQ + tg + 4]);
            afr[3] = __float_as_uint(qb[(g + 8) * LDQ + tg + 4]);
#pragma unroll
            for (int nt = 0; nt < 4; ++nt) {
                uint32_t bfr[2];
                bfr[0] = __float_as_uint(Kst[(nt * 8 + g) * LDK + kk * 8 + tg]);
                bfr[1] = __float_as_uint(Kst[(nt * 8 + g) * LDK + kk * 8 + tg + 4]);
                mma_tf32(sacc[nt], afr, bfr);
            }
        }

        // causal mask
        if (j * FBC + FBC - 1 > rbase) {
#pragma unroll
            for (int nt = 0; nt < 4; ++nt) {
                int c0 = j * FBC + nt * 8 + 2 * tg;
                if (c0 > rbase + g)         sacc[nt][0] = -1e30f;
                if (c0 + 1 > rbase + g)     sacc[nt][1] = -1e30f;
                if (c0 > rbase + g + 8)     sacc[nt][2] = -1e30f;
                if (c0 + 1 > rbase + g + 8) sacc[nt][3] = -1e30f;
            }
        }

        // online softmax
        float tm0 = -1e30f, tm1 = -1e30f;
#pragma unroll
        for (int nt = 0; nt < 4; ++nt) {
            tm0 = fmaxf(tm0, fmaxf(sacc[nt][0], sacc[nt][1]));
            tm1 = fmaxf(tm1, fmaxf(sacc[nt][2], sacc[nt][3]));
        }
        tm0 = fmaxf(tm0, __shfl_xor_sync(0xffffffffu, tm0, 1));
        tm0 = fmaxf(tm0, __shfl_xor_sync(0xffffffffu, tm0, 2));
        tm1 = fmaxf(tm1, __shfl_xor_sync(0xffffffffu, tm1, 1));
        tm1 = fmaxf(tm1, __shfl_xor_sync(0xffffffffu, tm1, 2));
        float mn0 = fmaxf(mrow0, tm0), mn1 = fmaxf(mrow1, tm1);
        float al0 = __expf(mrow0 - mn0), al1 = __expf(mrow1 - mn1);
        float rs0 = 0.f, rs1 = 0.f;
#pragma unroll
        for (int nt = 0; nt < 4; ++nt) {
            sacc[nt][0] = __expf(sacc[nt][0] - mn0);
            sacc[nt][1] = __expf(sacc[nt][1] - mn0);
            sacc[nt][2] = __expf(sacc[nt][2] - mn1);
            sacc[nt][3] = __expf(sacc[nt][3] - mn1);
            rs0 += sacc[nt][0] + sacc[nt][1];
            rs1 += sacc[nt][2] + sacc[nt][3];
        }
        rs0 += __shfl_xor_sync(0xffffffffu, rs0, 1);
        rs0 += __shfl_xor_sync(0xffffffffu, rs0, 2);
        rs1 += __shfl_xor_sync(0xffffffffu, rs1, 1);
        rs1 += __shfl_xor_sync(0xffffffffu, rs1, 2);
        lrow0 = lrow0 * al0 + rs0;
        lrow1 = lrow1 * al1 + rs1;
        mrow0 = mn0; mrow1 = mn1;
#pragma unroll
        for (int nt = 0; nt < 16; ++nt) {
            o[nt][0] *= al0; o[nt][1] *= al0;
            o[nt][2] *= al1; o[nt][3] *= al1;
        }

        // stage P (tf32)
#pragma unroll
        for (int nt = 0; nt < 4; ++nt) {
            int c = nt * 8 + 2 * tg;
            pw[g * LDP + c]           = f2tf32f(sacc[nt][0]);
            pw[g * LDP + c + 1]       = f2tf32f(sacc[nt][1]);
            pw[(g + 8) * LDP + c]     = f2tf32f(sacc[nt][2]);
            pw[(g + 8) * LDP + c + 1] = f2tf32f(sacc[nt][3]);
        }
        __syncwarp();

        // O += P @ V
#pragma unroll
        for (int kt = 0; kt < FBC / 8; ++kt) {
            uint32_t afr[4];
            afr[0] = __float_as_uint(pw[g * LDP + kt * 8 + tg]);
            afr[1] = __float_as_uint(pw[(g + 8) * LDP + kt * 8 + tg]);
            afr[2] = __float_as_uint(pw[g * LDP + kt * 8 + tg + 4]);
            afr[3] = __float_as_uint(pw[(g + 8) * LDP + kt * 8 + tg + 4]);
#pragma unroll
            for (int nt = 0; nt < 16; ++nt) {
                uint32_t bfr[2];
                bfr[0] = __float_as_uint(Vst[(kt * 8 + tg) * LDV + nt * 8 + g]);
                bfr[1] = __float_as_uint(Vst[(kt * 8 + tg + 4) * LDV + nt * 8 + g]);
                mma_tf32(o[nt], afr, bfr);
            }
        }
        __syncthreads();
    }

    float inv0 = 1.f / lrow0, inv1 = 1.f / lrow1;
    float* Obase = O + ((size_t)(b * S_ + rbase)) * H_ + h * HD_;
#pragma unroll
    for (int nt = 0; nt < 16; ++nt) {
        int c = nt * 8 + 2 * tg;
        *(float2*)(Obase + (size_t)g * H_ + c) =
            make_float2(f2tf32f(o[nt][0] * inv0), f2tf32f(o[nt][1] * inv0));
        *(float2*)(Obase + (size_t)(g + 8) * H_ + c) =
            make_float2(f2tf32f(o[nt][2] * inv1), f2tf32f(o[nt][3] * inv1));
    }
}

// ---------------- external memory attention (memory bound) ----------------
__global__ __launch_bounds__(256)
void ext_attn_kernel(const float* __restrict__ AO, const float* __restrict__ EK,
                     const float* __restrict__ EV, float* __restrict__ EC) {
    int widx = (blockIdx.x * blockDim.x + threadIdx.x) >> 5;
    int lane = threadIdx.x & 31;
    int q  = widx & (S_ - 1);
    int bh = widx >> 11;
    int b = bh >> 4, h = bh & 15;

    size_t aoff = ((size_t)b * S_ + q) * H_ + h * HD_ + lane * 4;
    float4 eq = *(const float4*)(AO + aoff);
    eq.x *= SCALE_; eq.y *= SCALE_; eq.z *= SCALE_; eq.w *= SCALE_;

    size_t base = ((size_t)bh * S_ + q) * (KE_ * HD_) + lane * 4;
    float s[KE_];
#pragma unroll
    for (int kk = 0; kk < KE_; ++kk) {
        float4 kv = *(const float4*)(EK + base + kk * HD_);
        s[kk] = eq.x * kv.x + eq.y * kv.y + eq.z * kv.z + eq.w * kv.w;
    }
#pragma unroll
    for (int kk = 0; kk < KE_; ++kk)
#pragma unroll
        for (int off = 16; off > 0; off >>= 1)
            s[kk] += __shfl_xor_sync(0xffffffffu, s[kk], off);

    float m = s[0];
#pragma unroll
    for (int kk = 1; kk < KE_; ++kk) m = fmaxf(m, s[kk]);
    float sum = 0.f;
#pragma unroll
    for (int kk = 0; kk < KE_; ++kk) { s[kk] = __expf(s[kk] - m); sum += s[kk]; }
    float inv = 1.f / sum;

    float4 acc = make_float4(0.f, 0.f, 0.f, 0.f);
#pragma unroll
    for (int kk = 0; kk < KE_; ++kk) {
        float4 vv = *(const float4*)(EV + base + kk * HD_);
        float wgt = s[kk] * inv;
        acc.x += wgt * vv.x; acc.y += wgt * vv.y;
        acc.z += wgt * vv.z; acc.w += wgt * vv.w;
    }
    *(float4*)(EC + aoff) = make_float4(f2tf32f(acc.x), f2tf32f(acc.y),
                                        f2tf32f(acc.z), f2tf32f(acc.w));
}

// ---------------- gate ----------------
__global__ __launch_bounds__(256)
void gate_kernel(const float* __restrict__ X, const float* __restrict__ Wg,
                 const float* __restrict__ bg, float* __restrict__ gate) {
    int row  = (blockIdx.x * blockDim.x + threadIdx.x) >> 5;
    int lane = threadIdx.x & 31;
    const float* xr = X + (size_t)row * H_;
    float a0 = 0.f, a1 = 0.f;
    for (int k = lane; k < H_; k += 32) {
        float x = xr[k];
        a0 += x * Wg[k * 3];
        a1 += x * Wg[k * 3 + 1];
    }
#pragma unroll
    for (int off = 16; off > 0; off >>= 1) {
        a0 += __shfl_xor_sync(0xffffffffu, a0, off);
        a1 += __shfl_xor_sync(0xffffffffu, a1, off);
    }
    if (lane == 0) {
        a0 += bg[0]; a1 += bg[1];
        float m = fmaxf(a0, a1);
        float e0 = __expf(a0 - m), e1 = __expf(a1 - m);
        float inv = 1.f / (e0 + e1);
        gate[row * 2]     = e0 * inv;
        gate[row * 2 + 1] = e1 * inv;
    }
}

// ---------------- launch ----------------
extern "C" void kernel_launch(void* const* d_in, const int* in_sizes, int n_in,
                              void* d_out, int out_size) {
    const float* X  = (const float*)d_in[0];
    const float* EK = (const float*)d_in[1];
    const float* EV = (const float*)d_in[2];
    const float* W_in[5] = {(const float*)d_in[3], (const float*)d_in[4],
                            (const float*)d_in[5], (const float*)d_in[6],
                            (const float*)d_in[7]};   // Wq, Wk, Wv, Wo, We
    const float* Wg = (const float*)d_in[8];
    const float* bg = (const float*)d_in[9];
    float* out = (float*)d_out;

    float *q, *k, *v, *ctx, *ao, *ec, *xt, *wt, *gt;
    cudaGetSymbolAddress((void**)&q,   g_q);
    cudaGetSymbolAddress((void**)&k,   g_k);
    cudaGetSymbolAddress((void**)&v,   g_v);
    cudaGetSymbolAddress((void**)&ctx, g_ctx);
    cudaGetSymbolAddress((void**)&ao,  g_ao);
    cudaGetSymbolAddress((void**)&ec,  g_ec);
    cudaGetSymbolAddress((void**)&xt,  g_xt);
    cudaGetSymbolAddress((void**)&wt,  g_wt);
    cudaGetSymbolAddress((void**)&gt,  g_gate);

    cudaFuncSetAttribute(gemm_v3<1,0>, cudaFuncAttributeMaxDynamicSharedMemorySize, GEMM_SMEM);
    cudaFuncSetAttribute(gemm_v3<0,0>, cudaFuncAttributeMaxDynamicSharedMemorySize, GEMM_SMEM);
    cudaFuncSetAttribute(gemm_v3<0,1>, cudaFuncAttributeMaxDynamicSharedMemorySize, GEMM_SMEM);
    cudaFuncSetAttribute(flash_kernel, cudaFuncAttributeMaxDynamicSharedMemorySize, FLASH_SMEM);

    // pre-pass: round X, transpose+round weights
    cvt_tf32_kernel<<<(M_ * H_ / 4) / 256, 256>>>((const float4*)X, (float4*)xt);
    for (int i = 0; i < 5; ++i)
        transpose_tf32_kernel<<<dim3(64, 64), 256>>>(W_in[i], wt + (size_t)i * H_ * H_);

    dim3 ggrid(H_ / 128, M_ / 128);   // (16, 64)
    const size_t WSZ = (size_t)H_ * H_;

    gemm_v3<1,0><<<ggrid, 128, GEMM_SMEM>>>(xt, wt + 0 * WSZ, q,  nullptr, nullptr);
    gemm_v3<1,0><<<ggrid, 128, GEMM_SMEM>>>(xt, wt + 1 * WSZ, k,  nullptr, nullptr);
    gemm_v3<1,0><<<ggrid, 128, GEMM_SMEM>>>(xt, wt + 2 * WSZ, v,  nullptr, nullptr);

    flash_kernel<<<dim3(S_ / FBR, B_ * NH_), 256, FLASH_SMEM>>>(q, k, v, ctx);

    gemm_v3<0,0><<<ggrid, 128, GEMM_SMEM>>>(ctx, wt + 3 * WSZ, ao, nullptr, nullptr);

    gate_kernel<<<M_ / 8, 256>>>(X, Wg, bg, gt);
    ext_attn_kernel<<<(B_ * NH_ * S_) / 8, 256>>>(ao, EK, EV, ec);

    gemm_v3<0,1><<<ggrid, 128, GEMM_SMEM>>>(ec, wt + 4 * WSZ, out, ao, gt);
}